// round 1
// baseline (speedup 1.0000x reference)
#include <cuda_runtime.h>

// Problem constants
#define NB    16
#define NPTS  4096
#define SPTS  1024
#define COLS  65536      // NB*NPTS
#define JCOLS 16384      // NB*SPTS

// Scratch (device globals; allocation-free at runtime)
__device__ float g_Z[3u * 16384u * 256u];   // Z[k][j][o], o contiguous  (48 MB)
__device__ float g_Y[256u * 65536u];        // pre-BN layer0 output      (64 MB)
__device__ float g_O2[128u * 65536u];       // pre-BN layer1 output      (32 MB)
__device__ int   g_idx[65536 * 3];
__device__ float g_w[65536 * 3];
__device__ float g_sum0[256], g_sq0[256], g_a0[256], g_c0[256];
__device__ float g_sum1[128], g_sq1[128], g_a1[128], g_c1[128];

__global__ void init_kernel() {
    int t = threadIdx.x;
    if (t < 256) { g_sum0[t] = 0.f; g_sq0[t] = 0.f; }
    if (t < 128) { g_sum1[t] = 0.f; g_sq1[t] = 0.f; }
}

// ---------------- 3-NN search + interpolation weights ----------------
__global__ void knn_kernel(const float* __restrict__ xyz1,
                           const float* __restrict__ xyz2) {
    __shared__ float sx[SPTS], sy[SPTS], sz[SPTS], sn[SPTS];
    const int t = threadIdx.x;
    const int b = blockIdx.x >> 4;
    const int qbase = (blockIdx.x & 15) << 8;
    const float* base2 = xyz2 + (size_t)b * 3 * SPTS;
    for (int i = t; i < SPTS; i += 256) {
        float x = base2[i], y = base2[SPTS + i], z = base2[2 * SPTS + i];
        sx[i] = x; sy[i] = y; sz[i] = z; sn[i] = x * x + y * y + z * z;
    }
    __syncthreads();
    const int n = qbase + t;
    const float* base1 = xyz1 + (size_t)b * 3 * NPTS;
    const float qx = base1[n], qy = base1[NPTS + n], qz = base1[2 * NPTS + n];
    const float qn = qx * qx + qy * qy + qz * qz;
    float d0 = 3.4e38f, d1 = 3.4e38f, d2 = 3.4e38f;
    int i0 = 0, i1 = 0, i2 = 0;
#pragma unroll 4
    for (int s = 0; s < SPTS; s++) {
        float d = qn + sn[s] - 2.f * (qx * sx[s] + qy * sy[s] + qz * sz[s]);
        if (d < d2) {
            if (d < d1) {
                if (d < d0) { d2 = d1; i2 = i1; d1 = d0; i1 = i0; d0 = d; i0 = s; }
                else        { d2 = d1; i2 = i1; d1 = d;  i1 = s; }
            } else          { d2 = d;  i2 = s; }
        }
    }
    const float r0 = 1.f / (d0 + 1e-8f);
    const float r1 = 1.f / (d1 + 1e-8f);
    const float r2 = 1.f / (d2 + 1e-8f);
    const float inv = 1.f / (r0 + r1 + r2);
    const int col = b * NPTS + n;
    g_idx[col * 3 + 0] = i0; g_idx[col * 3 + 1] = i1; g_idx[col * 3 + 2] = i2;
    g_w[col * 3 + 0] = r0 * inv; g_w[col * 3 + 1] = r1 * inv; g_w[col * 3 + 2] = r2 * inv;
}

// ---------------- GEMM Z[k][j][o] = sum_d W0[o][128+128k+d] * P2[b][d][s] ----------------
// M = 768 (k,o pairs), K = 128, cols = 16384. Output stored o-contiguous.
__global__ __launch_bounds__(256) void gemmZ(const float* __restrict__ w0,
                                             const float* __restrict__ p2) {
    __shared__ float As[8][128];
    __shared__ float Bs[8][128];
    const int t = threadIdx.x;
    const int tx = t & 15, ty = t >> 4;
    const int col0 = blockIdx.x * 128;
    const int m0 = blockIdx.y * 128;
    const int bb = col0 >> 10, sOff = col0 & 1023;
    const int am = t >> 1, ak = (t & 1) << 2;
    const int r = m0 + am;
    const int kgr = r >> 8, orow = r & 255;
    const float* aptr = w0 + (size_t)orow * 512 + 128 + kgr * 128 + ak;
    const int bk = t >> 5, bc = (t & 31) << 2;
    const float* bptr = p2 + ((size_t)bb * 128 + bk) * 1024 + sOff + bc;

    float acc[8][8];
#pragma unroll
    for (int i = 0; i < 8; i++)
#pragma unroll
        for (int j = 0; j < 8; j++) acc[i][j] = 0.f;

    float4 av = *(const float4*)aptr;
    float4 bv = *(const float4*)bptr;
#pragma unroll 1
    for (int kt = 0; kt < 16; kt++) {
        __syncthreads();
        As[ak][am] = av.x; As[ak + 1][am] = av.y; As[ak + 2][am] = av.z; As[ak + 3][am] = av.w;
        *(float4*)&Bs[bk][bc] = bv;
        __syncthreads();
        if (kt < 15) {
            av = *(const float4*)(aptr + (kt + 1) * 8);
            bv = *(const float4*)(bptr + (size_t)(kt + 1) * 8 * 1024);
        }
#pragma unroll
        for (int kk = 0; kk < 8; kk++) {
            float ar[8], br[8];
#pragma unroll
            for (int i = 0; i < 8; i++) ar[i] = As[kk][ty * 8 + i];
#pragma unroll
            for (int j = 0; j < 8; j++) br[j] = Bs[kk][tx * 8 + j];
#pragma unroll
            for (int i = 0; i < 8; i++)
#pragma unroll
                for (int j = 0; j < 8; j++) acc[i][j] = fmaf(ar[i], br[j], acc[i][j]);
        }
    }
    const int kg = m0 >> 8;
    const int obase = m0 - (kg << 8) + ty * 8;
#pragma unroll
    for (int j = 0; j < 8; j++) {
        const int col = col0 + tx * 8 + j;
        float* zp = g_Z + ((size_t)(kg * JCOLS + col)) * 256 + obase;
        *(float4*)zp       = make_float4(acc[0][j], acc[1][j], acc[2][j], acc[3][j]);
        *(float4*)(zp + 4) = make_float4(acc[4][j], acc[5][j], acc[6][j], acc[7][j]);
    }
}

// ---------------- GEMM Y = W0[:, :128] @ P1 + b0 + sum_k w_k * Z_k[:, idx_k]; stats ----------------
// M = 256, K = 128, cols = 65536.
__global__ __launch_bounds__(256) void gemmY(const float* __restrict__ w0,
                                             const float* __restrict__ p1,
                                             const float* __restrict__ bias0) {
    __shared__ float As[8][128];
    __shared__ float Bs[8][128];
    const int t = threadIdx.x;
    const int tx = t & 15, ty = t >> 4;
    const int col0 = blockIdx.x * 128;
    const int m0 = blockIdx.y * 128;
    const int bb = col0 >> 12, nOff = col0 & 4095;
    const int am = t >> 1, ak = (t & 1) << 2;
    const float* aptr = w0 + (size_t)(m0 + am) * 512 + ak;
    const int bk = t >> 5, bc = (t & 31) << 2;
    const float* bptr = p1 + ((size_t)bb * 128 + bk) * 4096 + nOff + bc;

    float acc[8][8];
#pragma unroll
    for (int i = 0; i < 8; i++)
#pragma unroll
        for (int j = 0; j < 8; j++) acc[i][j] = 0.f;

    float4 av = *(const float4*)aptr;
    float4 bv = *(const float4*)bptr;
#pragma unroll 1
    for (int kt = 0; kt < 16; kt++) {
        __syncthreads();
        As[ak][am] = av.x; As[ak + 1][am] = av.y; As[ak + 2][am] = av.z; As[ak + 3][am] = av.w;
        *(float4*)&Bs[bk][bc] = bv;
        __syncthreads();
        if (kt < 15) {
            av = *(const float4*)(aptr + (kt + 1) * 8);
            bv = *(const float4*)(bptr + (size_t)(kt + 1) * 8 * 4096);
        }
#pragma unroll
        for (int kk = 0; kk < 8; kk++) {
            float ar[8], br[8];
#pragma unroll
            for (int i = 0; i < 8; i++) ar[i] = As[kk][ty * 8 + i];
#pragma unroll
            for (int j = 0; j < 8; j++) br[j] = Bs[kk][tx * 8 + j];
#pragma unroll
            for (int i = 0; i < 8; i++)
#pragma unroll
                for (int j = 0; j < 8; j++) acc[i][j] = fmaf(ar[i], br[j], acc[i][j]);
        }
    }

    const int rowb = m0 + ty * 8;
    float bias[8];
#pragma unroll
    for (int i = 0; i < 8; i++) bias[i] = bias0[rowb + i];

    // gather epilogue: += bias + sum_k w_k * Z[k][b*1024+idx_k][row]
#pragma unroll
    for (int j = 0; j < 8; j++) {
        const int col = col0 + tx * 8 + j;
        const int ia = g_idx[col * 3], ib = g_idx[col * 3 + 1], ic = g_idx[col * 3 + 2];
        const float wa = g_w[col * 3], wb = g_w[col * 3 + 1], wc = g_w[col * 3 + 2];
        const int jb = (col >> 12) << 10;
        const float* z0 = g_Z + ((size_t)(jb + ia)) * 256 + rowb;
        const float* z1 = g_Z + ((size_t)(JCOLS + jb + ib)) * 256 + rowb;
        const float* z2 = g_Z + ((size_t)(2 * JCOLS + jb + ic)) * 256 + rowb;
        float4 p0 = *(const float4*)z0, p0b = *(const float4*)(z0 + 4);
        float4 q0 = *(const float4*)z1, q0b = *(const float4*)(z1 + 4);
        float4 r0 = *(const float4*)z2, r0b = *(const float4*)(z2 + 4);
        acc[0][j] += bias[0] + wa * p0.x  + wb * q0.x  + wc * r0.x;
        acc[1][j] += bias[1] + wa * p0.y  + wb * q0.y  + wc * r0.y;
        acc[2][j] += bias[2] + wa * p0.z  + wb * q0.z  + wc * r0.z;
        acc[3][j] += bias[3] + wa * p0.w  + wb * q0.w  + wc * r0.w;
        acc[4][j] += bias[4] + wa * p0b.x + wb * q0b.x + wc * r0b.x;
        acc[5][j] += bias[5] + wa * p0b.y + wb * q0b.y + wc * r0b.y;
        acc[6][j] += bias[6] + wa * p0b.z + wb * q0b.z + wc * r0b.z;
        acc[7][j] += bias[7] + wa * p0b.w + wb * q0b.w + wc * r0b.w;
    }

    const int colT = col0 + tx * 8;
#pragma unroll
    for (int i = 0; i < 8; i++) {
        const int row = rowb + i;
        float* yp = g_Y + (size_t)row * COLS + colT;
        *(float4*)yp       = make_float4(acc[i][0], acc[i][1], acc[i][2], acc[i][3]);
        *(float4*)(yp + 4) = make_float4(acc[i][4], acc[i][5], acc[i][6], acc[i][7]);
        float s = 0.f, q = 0.f;
#pragma unroll
        for (int j = 0; j < 8; j++) { s += acc[i][j]; q += acc[i][j] * acc[i][j]; }
#pragma unroll
        for (int off = 8; off; off >>= 1) {
            s += __shfl_xor_sync(0xffffffffu, s, off);
            q += __shfl_xor_sync(0xffffffffu, q, off);
        }
        if ((t & 15) == 0) { atomicAdd(&g_sum0[row], s); atomicAdd(&g_sq0[row], q); }
    }
}

__global__ void finalize0(const float* __restrict__ gamma, const float* __restrict__ beta) {
    const int t = threadIdx.x;  // 256
    const float mean = g_sum0[t] * (1.f / COLS);
    const float var = g_sq0[t] * (1.f / COLS) - mean * mean;
    const float a = gamma[t] * rsqrtf(var + 1e-5f);
    g_a0[t] = a;
    g_c0[t] = beta[t] - mean * a;
}

// ---------------- GEMM O2 = W1 @ relu(a0*Y + c0) + b1; stats ----------------
// M = 128, K = 256, cols = 65536.
__global__ __launch_bounds__(256) void gemmO2(const float* __restrict__ w1,
                                              const float* __restrict__ bias1) {
    __shared__ float As[8][128];
    __shared__ float Bs[8][128];
    const int t = threadIdx.x;
    const int tx = t & 15, ty = t >> 4;
    const int col0 = blockIdx.x * 128;
    const int am = t >> 1, ak = (t & 1) << 2;
    const float* aptr = w1 + (size_t)am * 256 + ak;
    const int bk = t >> 5, bc = (t & 31) << 2;
    const float* bptr = g_Y + (size_t)bk * COLS + col0 + bc;

    float acc[8][8];
#pragma unroll
    for (int i = 0; i < 8; i++)
#pragma unroll
        for (int j = 0; j < 8; j++) acc[i][j] = 0.f;

    float4 av = *(const float4*)aptr;
    float4 bv = *(const float4*)bptr;
    float sa = g_a0[bk], sc = g_c0[bk];
#pragma unroll 1
    for (int kt = 0; kt < 32; kt++) {
        __syncthreads();
        As[ak][am] = av.x; As[ak + 1][am] = av.y; As[ak + 2][am] = av.z; As[ak + 3][am] = av.w;
        float4 hv;
        hv.x = fmaxf(0.f, fmaf(sa, bv.x, sc));
        hv.y = fmaxf(0.f, fmaf(sa, bv.y, sc));
        hv.z = fmaxf(0.f, fmaf(sa, bv.z, sc));
        hv.w = fmaxf(0.f, fmaf(sa, bv.w, sc));
        *(float4*)&Bs[bk][bc] = hv;
        __syncthreads();
        if (kt < 31) {
            av = *(const float4*)(aptr + (kt + 1) * 8);
            bv = *(const float4*)(bptr + (size_t)(kt + 1) * 8 * COLS);
            sa = g_a0[(kt + 1) * 8 + bk];
            sc = g_c0[(kt + 1) * 8 + bk];
        }
#pragma unroll
        for (int kk = 0; kk < 8; kk++) {
            float ar[8], br[8];
#pragma unroll
            for (int i = 0; i < 8; i++) ar[i] = As[kk][ty * 8 + i];
#pragma unroll
            for (int j = 0; j < 8; j++) br[j] = Bs[kk][tx * 8 + j];
#pragma unroll
            for (int i = 0; i < 8; i++)
#pragma unroll
                for (int j = 0; j < 8; j++) acc[i][j] = fmaf(ar[i], br[j], acc[i][j]);
        }
    }

    const int rowb = ty * 8;
    const int colT = col0 + tx * 8;
#pragma unroll
    for (int i = 0; i < 8; i++) {
        const int row = rowb + i;
        const float bias = bias1[row];
#pragma unroll
        for (int j = 0; j < 8; j++) acc[i][j] += bias;
        float* op = g_O2 + (size_t)row * COLS + colT;
        *(float4*)op       = make_float4(acc[i][0], acc[i][1], acc[i][2], acc[i][3]);
        *(float4*)(op + 4) = make_float4(acc[i][4], acc[i][5], acc[i][6], acc[i][7]);
        float s = 0.f, q = 0.f;
#pragma unroll
        for (int j = 0; j < 8; j++) { s += acc[i][j]; q += acc[i][j] * acc[i][j]; }
#pragma unroll
        for (int off = 8; off; off >>= 1) {
            s += __shfl_xor_sync(0xffffffffu, s, off);
            q += __shfl_xor_sync(0xffffffffu, q, off);
        }
        if ((t & 15) == 0) { atomicAdd(&g_sum1[row], s); atomicAdd(&g_sq1[row], q); }
    }
}

__global__ void finalize1(const float* __restrict__ gamma, const float* __restrict__ beta) {
    const int t = threadIdx.x;  // 128
    const float mean = g_sum1[t] * (1.f / COLS);
    const float var = g_sq1[t] * (1.f / COLS) - mean * mean;
    const float a = gamma[t] * rsqrtf(var + 1e-5f);
    g_a1[t] = a;
    g_c1[t] = beta[t] - mean * a;
}

// ---------------- BN2 + ReLU + transpose store to output [B,128,N] ----------------
__global__ void bnout_kernel(float* __restrict__ out) {
    const int idx = blockIdx.x * 256 + threadIdx.x;   // float4 index
    const int e = idx * 4;
    const int row = e >> 16;          // channel 0..127
    const int col = e & 65535;        // b*4096 + n
    const int b = col >> 12, n = col & 4095;
    float4 v = *(const float4*)&g_O2[(size_t)row * COLS + col];
    const float a = g_a1[row], c = g_c1[row];
    float4 w;
    w.x = fmaxf(0.f, fmaf(a, v.x, c));
    w.y = fmaxf(0.f, fmaf(a, v.y, c));
    w.z = fmaxf(0.f, fmaf(a, v.z, c));
    w.w = fmaxf(0.f, fmaf(a, v.w, c));
    *(float4*)&out[((size_t)(b * 128 + row)) * 4096 + n] = w;
}

extern "C" void kernel_launch(void* const* d_in, const int* in_sizes, int n_in,
                              void* d_out, int out_size) {
    const float* xyz1 = (const float*)d_in[0];
    const float* xyz2 = (const float*)d_in[1];
    const float* p1   = (const float*)d_in[2];
    const float* p2   = (const float*)d_in[3];
    const float* w0   = (const float*)d_in[4];
    const float* b0   = (const float*)d_in[5];
    const float* g0   = (const float*)d_in[6];
    const float* be0  = (const float*)d_in[7];
    const float* w1   = (const float*)d_in[8];
    const float* b1   = (const float*)d_in[9];
    const float* g1   = (const float*)d_in[10];
    const float* be1  = (const float*)d_in[11];
    float* out = (float*)d_out;

    init_kernel<<<1, 256>>>();
    knn_kernel<<<256, 256>>>(xyz1, xyz2);
    gemmZ<<<dim3(JCOLS / 128, 6), 256>>>(w0, p2);
    gemmY<<<dim3(COLS / 128, 2), 256>>>(w0, p1, b0);
    finalize0<<<1, 256>>>(g0, be0);
    gemmO2<<<dim3(COLS / 128, 1), 256>>>(w1, b1);
    finalize1<<<1, 128>>>(g1, be1);
    bnout_kernel<<<(COLS * 128 / 4) / 256, 256>>>(out);
}

// round 2
// speedup vs baseline: 1.1485x; 1.1485x over previous
#include <cuda_runtime.h>
#include <cstdint>

#define NB    16
#define NPTS  4096
#define SPTS  1024
#define COLS  65536
#define JCOLS 16384

__device__ __align__(16) float g_Z[3u * 16384u * 256u];
__device__ __align__(16) float g_Y[256u * 65536u];
__device__ __align__(16) float g_O2[128u * 65536u];
__device__ __align__(16) float g_W0T[512 * 256];
__device__ __align__(16) float g_W1T[256 * 128];
__device__ int   g_idx[65536 * 3];
__device__ float g_w[65536 * 3];
__device__ float g_sum0[256], g_sq0[256], g_a0[256], g_c0[256];
__device__ float g_sum1[128], g_sq1[128], g_a1[128], g_c1[128];

__device__ __forceinline__ void cp16(uint32_t dst, const void* src) {
    asm volatile("cp.async.ca.shared.global [%0], [%1], 16;\n" :: "r"(dst), "l"(src));
}
__device__ __forceinline__ void cp_commit() { asm volatile("cp.async.commit_group;\n"); }
template<int N> __device__ __forceinline__ void cp_wait() {
    asm volatile("cp.async.wait_group %0;\n" :: "n"(N));
}

// ---------------- prep: zero stats + transpose weights ----------------
__global__ void prep_kernel(const float* __restrict__ w0, const float* __restrict__ w1) {
    const int idx = blockIdx.x * 256 + threadIdx.x;   // grid 512 -> 131072
    if (idx < 256) { g_sum0[idx] = 0.f; g_sq0[idx] = 0.f; }
    if (idx < 128) { g_sum1[idx] = 0.f; g_sq1[idx] = 0.f; }
    if (idx < 512 * 256) g_W0T[idx] = w0[(idx & 255) * 512 + (idx >> 8)];
    if (idx < 256 * 128) g_W1T[idx] = w1[(idx & 127) * 256 + (idx >> 7)];
}

// ---------------- 3-NN search + interpolation weights ----------------
__global__ void knn_kernel(const float* __restrict__ xyz1,
                           const float* __restrict__ xyz2) {
    __shared__ float sx[SPTS], sy[SPTS], sz[SPTS], sn[SPTS];
    const int t = threadIdx.x;
    const int b = blockIdx.x >> 4;
    const int qbase = (blockIdx.x & 15) << 8;
    const float* base2 = xyz2 + (size_t)b * 3 * SPTS;
    for (int i = t; i < SPTS; i += 256) {
        float x = base2[i], y = base2[SPTS + i], z = base2[2 * SPTS + i];
        sx[i] = x; sy[i] = y; sz[i] = z; sn[i] = x * x + y * y + z * z;
    }
    __syncthreads();
    const int n = qbase + t;
    const float* base1 = xyz1 + (size_t)b * 3 * NPTS;
    const float qx = base1[n], qy = base1[NPTS + n], qz = base1[2 * NPTS + n];
    const float qn = qx * qx + qy * qy + qz * qz;
    float d0 = 3.4e38f, d1 = 3.4e38f, d2 = 3.4e38f;
    int i0 = 0, i1 = 0, i2 = 0;
#pragma unroll 4
    for (int s = 0; s < SPTS; s++) {
        float d = qn + sn[s] - 2.f * (qx * sx[s] + qy * sy[s] + qz * sz[s]);
        if (d < d2) {
            if (d < d1) {
                if (d < d0) { d2 = d1; i2 = i1; d1 = d0; i1 = i0; d0 = d; i0 = s; }
                else        { d2 = d1; i2 = i1; d1 = d;  i1 = s; }
            } else          { d2 = d;  i2 = s; }
        }
    }
    const float r0 = 1.f / (d0 + 1e-8f);
    const float r1 = 1.f / (d1 + 1e-8f);
    const float r2 = 1.f / (d2 + 1e-8f);
    const float inv = 1.f / (r0 + r1 + r2);
    const int col = b * NPTS + n;
    g_idx[col * 3 + 0] = i0; g_idx[col * 3 + 1] = i1; g_idx[col * 3 + 2] = i2;
    g_w[col * 3 + 0] = r0 * inv; g_w[col * 3 + 1] = r1 * inv; g_w[col * 3 + 2] = r2 * inv;
}

// ---------------- GEMM Z: M=768 (k,o), K=128, cols=16384 ----------------
__global__ __launch_bounds__(256, 2) void gemmZ(const float* __restrict__ p2) {
    __shared__ __align__(16) float As[3][8][128];
    __shared__ __align__(16) float Bs[3][8][128];
    const int t = threadIdx.x;
    const int tx = t & 15, ty = t >> 4;
    const int col0 = blockIdx.x * 128;
    const int kg = blockIdx.y >> 1;
    const int o0 = (blockIdx.y & 1) * 128;
    const int bb = col0 >> 10, sOff = col0 & 1023;
    const int lk = t >> 5, lc = (t & 31) * 4;
    const float* aSrc = g_W0T + (size_t)(128 + kg * 128 + lk) * 256 + o0 + lc;
    const float* bSrc = p2 + ((size_t)bb * 128 + lk) * 1024 + sOff + lc;
    const uint32_t aDst = (uint32_t)__cvta_generic_to_shared(&As[0][lk][lc]);
    const uint32_t bDst = (uint32_t)__cvta_generic_to_shared(&Bs[0][lk][lc]);
    const uint32_t SB = 8 * 128 * 4;

    float acc[8][8];
#pragma unroll
    for (int i = 0; i < 8; i++)
#pragma unroll
        for (int j = 0; j < 8; j++) acc[i][j] = 0.f;

    cp16(aDst, aSrc); cp16(bDst, bSrc); cp_commit();
    cp16(aDst + SB, aSrc + 8 * 256); cp16(bDst + SB, bSrc + 8 * 1024); cp_commit();

    int ls = 2, cs = 0;
#pragma unroll 1
    for (int kt = 0; kt < 16; kt++) {
        cp_wait<1>();
        __syncthreads();
        if (kt + 2 < 16) {
            cp16(aDst + ls * SB, aSrc + (size_t)(kt + 2) * 8 * 256);
            cp16(bDst + ls * SB, bSrc + (size_t)(kt + 2) * 8 * 1024);
        }
        cp_commit();
        ls++; if (ls == 3) ls = 0;
#pragma unroll
        for (int kk = 0; kk < 8; kk++) {
            float ar[8], br[8];
            *(float4*)&ar[0] = *(const float4*)&As[cs][kk][ty * 8];
            *(float4*)&ar[4] = *(const float4*)&As[cs][kk][ty * 8 + 4];
            *(float4*)&br[0] = *(const float4*)&Bs[cs][kk][tx * 8];
            *(float4*)&br[4] = *(const float4*)&Bs[cs][kk][tx * 8 + 4];
#pragma unroll
            for (int i = 0; i < 8; i++)
#pragma unroll
                for (int j = 0; j < 8; j++) acc[i][j] = fmaf(ar[i], br[j], acc[i][j]);
        }
        cs++; if (cs == 3) cs = 0;
    }
    const int obase = o0 + ty * 8;
#pragma unroll
    for (int j = 0; j < 8; j++) {
        const int col = col0 + tx * 8 + j;
        float* zp = g_Z + ((size_t)(kg * JCOLS + col)) * 256 + obase;
        *(float4*)zp       = make_float4(acc[0][j], acc[1][j], acc[2][j], acc[3][j]);
        *(float4*)(zp + 4) = make_float4(acc[4][j], acc[5][j], acc[6][j], acc[7][j]);
    }
}

// ---------------- GEMM Y: M=256, K=128, cols=65536; gather + stats epilogue ----------------
__global__ __launch_bounds__(256, 2) void gemmY(const float* __restrict__ p1,
                                                const float* __restrict__ bias0) {
    __shared__ __align__(16) float As[3][8][128];
    __shared__ __align__(16) float Bs[3][8][128];
    const int t = threadIdx.x;
    const int tx = t & 15, ty = t >> 4;
    const int col0 = blockIdx.x * 128;
    const int m0 = blockIdx.y * 128;
    const int bb = col0 >> 12, nOff = col0 & 4095;
    const int lk = t >> 5, lc = (t & 31) * 4;
    const float* aSrc = g_W0T + (size_t)lk * 256 + m0 + lc;
    const float* bSrc = p1 + ((size_t)bb * 128 + lk) * 4096 + nOff + lc;
    const uint32_t aDst = (uint32_t)__cvta_generic_to_shared(&As[0][lk][lc]);
    const uint32_t bDst = (uint32_t)__cvta_generic_to_shared(&Bs[0][lk][lc]);
    const uint32_t SB = 8 * 128 * 4;

    float acc[8][8];
#pragma unroll
    for (int i = 0; i < 8; i++)
#pragma unroll
        for (int j = 0; j < 8; j++) acc[i][j] = 0.f;

    cp16(aDst, aSrc); cp16(bDst, bSrc); cp_commit();
    cp16(aDst + SB, aSrc + 8 * 256); cp16(bDst + SB, bSrc + 8 * 4096); cp_commit();

    int ls = 2, cs = 0;
#pragma unroll 1
    for (int kt = 0; kt < 16; kt++) {
        cp_wait<1>();
        __syncthreads();
        if (kt + 2 < 16) {
            cp16(aDst + ls * SB, aSrc + (size_t)(kt + 2) * 8 * 256);
            cp16(bDst + ls * SB, bSrc + (size_t)(kt + 2) * 8 * 4096);
        }
        cp_commit();
        ls++; if (ls == 3) ls = 0;
#pragma unroll
        for (int kk = 0; kk < 8; kk++) {
            float ar[8], br[8];
            *(float4*)&ar[0] = *(const float4*)&As[cs][kk][ty * 8];
            *(float4*)&ar[4] = *(const float4*)&As[cs][kk][ty * 8 + 4];
            *(float4*)&br[0] = *(const float4*)&Bs[cs][kk][tx * 8];
            *(float4*)&br[4] = *(const float4*)&Bs[cs][kk][tx * 8 + 4];
#pragma unroll
            for (int i = 0; i < 8; i++)
#pragma unroll
                for (int j = 0; j < 8; j++) acc[i][j] = fmaf(ar[i], br[j], acc[i][j]);
        }
        cs++; if (cs == 3) cs = 0;
    }

    const int rowb = m0 + ty * 8;
    float bias[8];
#pragma unroll
    for (int i = 0; i < 8; i++) bias[i] = bias0[rowb + i];

#pragma unroll
    for (int j = 0; j < 8; j++) {
        const int col = col0 + tx * 8 + j;
        const int ia = g_idx[col * 3], ib = g_idx[col * 3 + 1], ic = g_idx[col * 3 + 2];
        const float wa = g_w[col * 3], wb = g_w[col * 3 + 1], wc = g_w[col * 3 + 2];
        const int jb = (col >> 12) << 10;
        const float* z0 = g_Z + ((size_t)(jb + ia)) * 256 + rowb;
        const float* z1 = g_Z + ((size_t)(JCOLS + jb + ib)) * 256 + rowb;
        const float* z2 = g_Z + ((size_t)(2 * JCOLS + jb + ic)) * 256 + rowb;
        float4 p0 = *(const float4*)z0, p0b = *(const float4*)(z0 + 4);
        float4 q0 = *(const float4*)z1, q0b = *(const float4*)(z1 + 4);
        float4 r0 = *(const float4*)z2, r0b = *(const float4*)(z2 + 4);
        acc[0][j] += bias[0] + wa * p0.x  + wb * q0.x  + wc * r0.x;
        acc[1][j] += bias[1] + wa * p0.y  + wb * q0.y  + wc * r0.y;
        acc[2][j] += bias[2] + wa * p0.z  + wb * q0.z  + wc * r0.z;
        acc[3][j] += bias[3] + wa * p0.w  + wb * q0.w  + wc * r0.w;
        acc[4][j] += bias[4] + wa * p0b.x + wb * q0b.x + wc * r0b.x;
        acc[5][j] += bias[5] + wa * p0b.y + wb * q0b.y + wc * r0b.y;
        acc[6][j] += bias[6] + wa * p0b.z + wb * q0b.z + wc * r0b.z;
        acc[7][j] += bias[7] + wa * p0b.w + wb * q0b.w + wc * r0b.w;
    }

    const int colT = col0 + tx * 8;
#pragma unroll
    for (int i = 0; i < 8; i++) {
        const int row = rowb + i;
        float* yp = g_Y + (size_t)row * COLS + colT;
        *(float4*)yp       = make_float4(acc[i][0], acc[i][1], acc[i][2], acc[i][3]);
        *(float4*)(yp + 4) = make_float4(acc[i][4], acc[i][5], acc[i][6], acc[i][7]);
        float s = 0.f, q = 0.f;
#pragma unroll
        for (int j = 0; j < 8; j++) { s += acc[i][j]; q += acc[i][j] * acc[i][j]; }
#pragma unroll
        for (int off = 8; off; off >>= 1) {
            s += __shfl_xor_sync(0xffffffffu, s, off);
            q += __shfl_xor_sync(0xffffffffu, q, off);
        }
        if ((t & 15) == 0) { atomicAdd(&g_sum0[row], s); atomicAdd(&g_sq0[row], q); }
    }
}

__global__ void finalize0(const float* __restrict__ gamma, const float* __restrict__ beta) {
    const int t = threadIdx.x;
    const float mean = g_sum0[t] * (1.f / COLS);
    const float var = g_sq0[t] * (1.f / COLS) - mean * mean;
    const float a = gamma[t] * rsqrtf(var + 1e-5f);
    g_a0[t] = a;
    g_c0[t] = beta[t] - mean * a;
}

// ---------------- GEMM O2: M=128, K=256, cols=65536; BN0+ReLU on B; stats ----------------
__global__ __launch_bounds__(256, 2) void gemmO2(const float* __restrict__ bias1) {
    __shared__ __align__(16) float As[3][8][128];
    __shared__ __align__(16) float Bs[3][8][128];
    __shared__ float s_a0[256], s_c0[256];
    const int t = threadIdx.x;
    const int tx = t & 15, ty = t >> 4;
    const int col0 = blockIdx.x * 128;
    const int lk = t >> 5, lc = (t & 31) * 4;
    s_a0[t] = g_a0[t];
    s_c0[t] = g_c0[t];
    const float* aSrc = g_W1T + (size_t)lk * 128 + lc;
    const float* bSrc = g_Y + (size_t)lk * COLS + col0 + lc;
    const uint32_t aDst = (uint32_t)__cvta_generic_to_shared(&As[0][lk][lc]);
    const uint32_t bDst = (uint32_t)__cvta_generic_to_shared(&Bs[0][lk][lc]);
    const uint32_t SB = 8 * 128 * 4;

    float acc[8][8];
#pragma unroll
    for (int i = 0; i < 8; i++)
#pragma unroll
        for (int j = 0; j < 8; j++) acc[i][j] = 0.f;

    cp16(aDst, aSrc); cp16(bDst, bSrc); cp_commit();
    cp16(aDst + SB, aSrc + 8 * 128); cp16(bDst + SB, bSrc + (size_t)8 * COLS); cp_commit();

    int ls = 2, cs = 0;
#pragma unroll 1
    for (int kt = 0; kt < 32; kt++) {
        cp_wait<1>();
        __syncthreads();
        if (kt + 2 < 32) {
            cp16(aDst + ls * SB, aSrc + (size_t)(kt + 2) * 8 * 128);
            cp16(bDst + ls * SB, bSrc + (size_t)(kt + 2) * 8 * COLS);
        }
        cp_commit();
        ls++; if (ls == 3) ls = 0;
#pragma unroll
        for (int kk = 0; kk < 8; kk++) {
            const float sa = s_a0[kt * 8 + kk];
            const float sc = s_c0[kt * 8 + kk];
            float ar[8], br[8];
            *(float4*)&ar[0] = *(const float4*)&As[cs][kk][ty * 8];
            *(float4*)&ar[4] = *(const float4*)&As[cs][kk][ty * 8 + 4];
            *(float4*)&br[0] = *(const float4*)&Bs[cs][kk][tx * 8];
            *(float4*)&br[4] = *(const float4*)&Bs[cs][kk][tx * 8 + 4];
#pragma unroll
            for (int j = 0; j < 8; j++) br[j] = fmaxf(0.f, fmaf(sa, br[j], sc));
#pragma unroll
            for (int i = 0; i < 8; i++)
#pragma unroll
                for (int j = 0; j < 8; j++) acc[i][j] = fmaf(ar[i], br[j], acc[i][j]);
        }
        cs++; if (cs == 3) cs = 0;
    }

    const int rowb = ty * 8;
    const int colT = col0 + tx * 8;
#pragma unroll
    for (int i = 0; i < 8; i++) {
        const int row = rowb + i;
        const float bias = bias1[row];
#pragma unroll
        for (int j = 0; j < 8; j++) acc[i][j] += bias;
        float* op = g_O2 + (size_t)row * COLS + colT;
        *(float4*)op       = make_float4(acc[i][0], acc[i][1], acc[i][2], acc[i][3]);
        *(float4*)(op + 4) = make_float4(acc[i][4], acc[i][5], acc[i][6], acc[i][7]);
        float s = 0.f, q = 0.f;
#pragma unroll
        for (int j = 0; j < 8; j++) { s += acc[i][j]; q += acc[i][j] * acc[i][j]; }
#pragma unroll
        for (int off = 8; off; off >>= 1) {
            s += __shfl_xor_sync(0xffffffffu, s, off);
            q += __shfl_xor_sync(0xffffffffu, q, off);
        }
        if ((t & 15) == 0) { atomicAdd(&g_sum1[row], s); atomicAdd(&g_sq1[row], q); }
    }
}

__global__ void finalize1(const float* __restrict__ gamma, const float* __restrict__ beta) {
    const int t = threadIdx.x;
    const float mean = g_sum1[t] * (1.f / COLS);
    const float var = g_sq1[t] * (1.f / COLS) - mean * mean;
    const float a = gamma[t] * rsqrtf(var + 1e-5f);
    g_a1[t] = a;
    g_c1[t] = beta[t] - mean * a;
}

// ---------------- BN2 + ReLU + transpose store ----------------
__global__ void bnout_kernel(float* __restrict__ out) {
    const int idx = blockIdx.x * 256 + threadIdx.x;
    const int e = idx * 4;
    const int row = e >> 16;
    const int col = e & 65535;
    const int b = col >> 12, n = col & 4095;
    float4 v = *(const float4*)&g_O2[(size_t)row * COLS + col];
    const float a = g_a1[row], c = g_c1[row];
    float4 w;
    w.x = fmaxf(0.f, fmaf(a, v.x, c));
    w.y = fmaxf(0.f, fmaf(a, v.y, c));
    w.z = fmaxf(0.f, fmaf(a, v.z, c));
    w.w = fmaxf(0.f, fmaf(a, v.w, c));
    *(float4*)&out[((size_t)(b * 128 + row)) * 4096 + n] = w;
}

extern "C" void kernel_launch(void* const* d_in, const int* in_sizes, int n_in,
                              void* d_out, int out_size) {
    const float* xyz1 = (const float*)d_in[0];
    const float* xyz2 = (const float*)d_in[1];
    const float* p1   = (const float*)d_in[2];
    const float* p2   = (const float*)d_in[3];
    const float* w0   = (const float*)d_in[4];
    const float* b0   = (const float*)d_in[5];
    const float* g0   = (const float*)d_in[6];
    const float* be0  = (const float*)d_in[7];
    const float* w1   = (const float*)d_in[8];
    const float* b1   = (const float*)d_in[9];
    const float* g1   = (const float*)d_in[10];
    const float* be1  = (const float*)d_in[11];
    float* out = (float*)d_out;

    prep_kernel<<<512, 256>>>(w0, w1);
    knn_kernel<<<256, 256>>>(xyz1, xyz2);
    gemmZ<<<dim3(JCOLS / 128, 6), 256>>>(p2);
    gemmY<<<dim3(COLS / 128, 2), 256>>>(p1, b0);
    finalize0<<<1, 256>>>(g0, be0);
    gemmO2<<<dim3(COLS / 128, 1), 256>>>(b1);
    finalize1<<<1, 128>>>(g1, be1);
    bnout_kernel<<<(COLS * 128 / 4) / 256, 256>>>(out);
}